// round 14
// baseline (speedup 1.0000x reference)
#include <cuda_runtime.h>
#include <math_constants.h>
#include <cstdint>

#define BCL   16
#define NPTS  4096
#define MCTR  1024
#define CIN   64
#define HID   64
#define OUTC  128
#define KNBR  64
#define NCTR  (BCL*MCTR)

typedef unsigned long long ull;

// ---------------- device scratch (no allocs allowed) ----------------
__device__ float g_F1[(size_t)BCL*NPTS*HID];   // 16 MB: feat @ W1[0:64]
__device__ int   g_nbr[(size_t)NCTR*KNBR];
__device__ int   g_cnt[NCTR];

// d2 with NO fma contraction, left-assoc — must match XLA's sum((a-b)**2, -1)
__device__ __forceinline__ float d2_nofma(float dx, float dy, float dz) {
    return __fadd_rn(__fadd_rn(__fmul_rn(dx, dx), __fmul_rn(dy, dy)), __fmul_rn(dz, dz));
}

// ---------------- packed f32x2 helpers (sm_103a) ----------------
__device__ __forceinline__ ull pk2(float lo, float hi) {
    ull r;
    asm("mov.b64 %0, {%1, %2};" : "=l"(r)
        : "r"(__float_as_uint(lo)), "r"(__float_as_uint(hi)));
    return r;
}
__device__ __forceinline__ float2 upk2(ull v) {
    unsigned lo, hi;
    asm("mov.b64 {%0, %1}, %2;" : "=r"(lo), "=r"(hi) : "l"(v));
    return make_float2(__uint_as_float(lo), __uint_as_float(hi));
}
__device__ __forceinline__ ull mul2(ull a, ull b) {
    ull r; asm("mul.rn.f32x2 %0, %1, %2;" : "=l"(r) : "l"(a), "l"(b)); return r;
}
__device__ __forceinline__ ull add2(ull a, ull b) {
    ull r; asm("add.rn.f32x2 %0, %1, %2;" : "=l"(r) : "l"(a), "l"(b)); return r;
}
__device__ __forceinline__ void fma2(ull& d, ull a, ull b) {
    asm("fma.rn.f32x2 %0, %1, %2, %0;" : "+l"(d) : "l"(a), "l"(b));
}

// =====================================================================
// Kernel 1: FPS. 1 block/cloud, 256 threads x 16 pts in registers.
// (R10 version — measured best)
// =====================================================================
__global__ __launch_bounds__(256) void fps_kernel(
    const float* __restrict__ pos,
    float* __restrict__ out_centers, float* __restrict__ out_batch)
{
    const int b   = blockIdx.x;
    const int tid = threadIdx.x;
    const float* P = pos + (size_t)b * NPTS * 3;

    ull pxp[8], pyp[8], pzp[8];
    float dd[16];
#pragma unroll
    for (int q = 0; q < 8; q++) {
        int jA = tid + (q << 9);
        int jB = jA + 256;
        pxp[q] = pk2(P[3*jA],   P[3*jB]);
        pyp[q] = pk2(P[3*jA+1], P[3*jB+1]);
        pzp[q] = pk2(P[3*jA+2], P[3*jB+2]);
    }
#pragma unroll
    for (int i = 0; i < 16; i++) dd[i] = CUDART_INF_F;

    __shared__ ull s_wk[2][8];
    const int lane = tid & 31, wid = tid >> 5;

    int jwin = 0;
    for (int m = 0; m < MCTR; m++) {
        float cx = P[3*jwin], cy = P[3*jwin+1], cz = P[3*jwin+2];
        if (tid == 0) {
            size_t o = (size_t)b * MCTR + m;
            out_centers[o*3+0] = cx;
            out_centers[o*3+1] = cy;
            out_centers[o*3+2] = cz;
            out_batch[o] = (float)b;
        }
        if (m == MCTR - 1) break;

        const ull ncx = pk2(-cx, -cx), ncy = pk2(-cy, -cy), ncz = pk2(-cz, -cz);
        float bd = -1.0f; int bj = 0;
#pragma unroll
        for (int q = 0; q < 8; q++) {
            ull dx = add2(pxp[q], ncx);
            ull dy = add2(pyp[q], ncy);
            ull dz = add2(pzp[q], ncz);
            ull d2p = add2(add2(mul2(dx, dx), mul2(dy, dy)), mul2(dz, dz));
            float2 d = upk2(d2p);
            float nA = fminf(dd[2*q],   d.x);
            float nB = fminf(dd[2*q+1], d.y);
            dd[2*q] = nA; dd[2*q+1] = nB;
            if (nA > bd) { bd = nA; bj = tid + (q << 9); }
            if (nB > bd) { bd = nB; bj = tid + (q << 9) + 256; }
        }
        ull key = ((ull)__float_as_uint(bd) << 32) | (ull)(0xFFFFFFFFu - (unsigned)bj);
#pragma unroll
        for (int off = 16; off; off >>= 1) {
            ull ok = __shfl_down_sync(0xFFFFFFFFu, key, off);
            if (ok > key) key = ok;
        }
        if (lane == 0) s_wk[m & 1][wid] = key;
        __syncthreads();
        ull k0 = s_wk[m & 1][0];
#pragma unroll
        for (int w = 1; w < 8; w++) {
            ull kw = s_wk[m & 1][w];
            if (kw > k0) k0 = kw;
        }
        jwin = (int)(0xFFFFFFFFu - (unsigned)(k0 & 0xFFFFFFFFu));
    }
}

// =====================================================================
// Kernel 2: F1 = feat @ W1[0:64]  (unchanged)
// =====================================================================
__global__ __launch_bounds__(64) void f1_kernel(
    const float* __restrict__ feat, const float* __restrict__ W1)
{
    __shared__ float sf[64][65];
    __shared__ float sw[64][64];
    const int p0  = blockIdx.x * 64;
    const int tid = threadIdx.x;

    for (int i = tid; i < 4096; i += 64) sw[i >> 6][i & 63] = W1[i];
    for (int i = tid; i < 4096; i += 64) {
        int p = i >> 6, c = i & 63;
        sf[p][c] = feat[(size_t)(p0 + p) * CIN + c];
    }
    __syncthreads();

    const int c = tid;
    for (int p = 0; p < 64; p += 4) {
        float a0 = 0.f, a1 = 0.f, a2 = 0.f, a3 = 0.f;
#pragma unroll
        for (int k = 0; k < 64; k++) {
            float w = sw[k][c];
            a0 += sf[p+0][k] * w;
            a1 += sf[p+1][k] * w;
            a2 += sf[p+2][k] * w;
            a3 += sf[p+3][k] * w;
        }
        g_F1[(size_t)(p0+p+0)*HID + c] = a0;
        g_F1[(size_t)(p0+p+1)*HID + c] = a1;
        g_F1[(size_t)(p0+p+2)*HID + c] = a2;
        g_F1[(size_t)(p0+p+3)*HID + c] = a3;
    }
}

// =====================================================================
// Kernel 3: exact K-nearest-in-ball selection — COMPACT-FIRST.
// Phase 1 compacts valid (bits,idx) pairs; radix passes and emission
// sweep only cnt (~140) elements instead of 4096. Same T/k/tie rules.
// =====================================================================
__global__ __launch_bounds__(128) void select_kernel(
    const float* __restrict__ pos, const float* __restrict__ centers)
{
    const int cid = blockIdx.x;
    const int b   = cid >> 10;
    const int tid = threadIdx.x;
    const int lane = tid & 31, wid = tid >> 5;
    const float* P = pos + (size_t)b * NPTS * 3;

    __shared__ unsigned        cb[NPTS];     // compact d2 bits (worst case 4096)
    __shared__ unsigned short  ci[NPTS];     // compact original index
    __shared__ int hist[256];
    __shared__ int s_wsum[4];
    __shared__ int s_cnt, s_pos, s_bin, s_klt, s_eqn;
    __shared__ int s_eq[64];

    const float cx = centers[(size_t)cid*3+0];
    const float cy = centers[(size_t)cid*3+1];
    const float cz = centers[(size_t)cid*3+2];
    const float R2 = (float)(0.2 * 0.2);

    if (tid == 0) { s_cnt = 0; s_pos = 0; s_eqn = 0; }
    __syncthreads();

    // ---- phase 1: distances + compaction of valid entries ----
    for (int j = tid; j < NPTS; j += 128) {
        float dx = cx - P[3*j], dy = cy - P[3*j+1], dz = cz - P[3*j+2];
        float d2 = d2_nofma(dx, dy, dz);
        if (d2 < R2) {
            int p = atomicAdd(&s_cnt, 1);
            cb[p] = __float_as_uint(d2);
            ci[p] = (unsigned short)j;
        }
    }
    __syncthreads();
    const int cnt = s_cnt;

    if (cnt <= KNBR) {                        // take every valid neighbor
        for (int p = tid; p < KNBR; p += 128)
            g_nbr[(size_t)cid*KNBR + p] = (p < cnt) ? (int)ci[p] : 0;
        if (tid == 0) g_cnt[cid] = cnt;
        return;
    }

    // ---- radix select over the COMPACT list: 64th smallest ----
    unsigned pref = 0; int k = KNBR;
    for (int sh = 24; sh >= 0; sh -= 8) {
        for (int i = tid; i < 256; i += 128) hist[i] = 0;
        __syncthreads();
        unsigned hm = (sh == 24) ? 0u : (0xFFFFFFFFu << (sh + 8));
        for (int p = tid; p < cnt; p += 128) {
            unsigned v = cb[p];
            if ((v & hm) == pref)
                atomicAdd(&hist[(v >> sh) & 255], 1);
        }
        __syncthreads();
        // parallel 256-bin scan (thread owns bins 2t, 2t+1)
        {
            int h0 = hist[2*tid], h1 = hist[2*tid+1];
            int loc = h0 + h1;
            int inc = loc;
#pragma unroll
            for (int off = 1; off < 32; off <<= 1) {
                int t = __shfl_up_sync(0xFFFFFFFFu, inc, off);
                if (lane >= off) inc += t;
            }
            if (lane == 31) s_wsum[wid] = inc;
            __syncthreads();
            int woff = 0;
#pragma unroll
            for (int w = 0; w < 4; w++) if (w < wid) woff += s_wsum[w];
            int cumIncl   = inc + woff;
            int cumBefore = cumIncl - loc;
            if (cumBefore < k && k <= cumBefore + h0) {
                s_bin = 2*tid;     s_klt = k - cumBefore;
            } else if (cumBefore + h0 < k && k <= cumIncl) {
                s_bin = 2*tid + 1; s_klt = k - cumBefore - h0;
            }
        }
        __syncthreads();
        pref |= ((unsigned)s_bin) << sh;
        k = s_klt;
        __syncthreads();
    }
    const unsigned T = pref;   // exact 64th smallest; k = rank within equals

    // ---- emission from the compact list ----
    for (int p = tid; p < cnt; p += 128) {
        unsigned v = cb[p];
        if (v < T) {
            int q = atomicAdd(&s_pos, 1);
            g_nbr[(size_t)cid*KNBR + q] = (int)ci[p];
        } else if (v == T) {
            int e = atomicAdd(&s_eqn, 1);
            if (e < 64) s_eq[e] = (int)ci[p];
        }
    }
    __syncthreads();
    if (tid == 0) {
        int base = s_pos;                 // = 64 - k
        int ne = s_eqn < 64 ? s_eqn : 64;
        for (int a = 1; a < ne; a++) {    // ascending index (stable-top_k ties)
            int key = s_eq[a], t2 = a - 1;
            while (t2 >= 0 && s_eq[t2] > key) { s_eq[t2+1] = s_eq[t2]; t2--; }
            s_eq[t2+1] = key;
        }
        for (int a = 0; a < k; a++) g_nbr[(size_t)cid*KNBR + base + a] = s_eq[a];
        g_cnt[cid] = KNBR;
    }
}

// =====================================================================
// Kernel 4: fused MLP + masked max (R11 version, measured best 610us).
// =====================================================================
#define HT_STRIDE 136     // ht[64][136]  (k-major view)
#define H2_STRIDE 68      // h2row[128][68] (row-major swizzled view)

struct __align__(16) Mlp2Smem {
    float  buf[64 * HT_STRIDE];
    float  cmax[16][132];
    float4 wb1[64];
    float  b2[64];
    float  b3[128];
    int    cnt[2];
};

__global__ __launch_bounds__(128, 4) void mlp2_kernel(
    const float* __restrict__ pos, const float* __restrict__ centers,
    const float* __restrict__ W1, const float* __restrict__ b1,
    const float* __restrict__ W2, const float* __restrict__ b2,
    const float* __restrict__ W3, const float* __restrict__ b3,
    float* __restrict__ out)
{
    __shared__ Mlp2Smem S;

    const int c0  = blockIdx.x * 2;
    const int b   = c0 >> 10;
    const int tid = threadIdx.x;

    if (tid < 64) {
        S.wb1[tid] = make_float4(W1[4096 + tid], W1[4160 + tid], W1[4224 + tid], b1[tid]);
        S.b2[tid]  = b2[tid];
    }
    S.b3[tid] = b3[tid];
    if (tid < 2) S.cnt[tid] = g_cnt[c0 + tid];

    const int n      = tid;
    const int center = n >> 6;
    const int jl     = g_nbr[(size_t)c0 * KNBR + n];
    const float* Pp  = pos + ((size_t)b * NPTS + jl) * 3;
    const float* Cc  = centers + (size_t)(c0 + center) * 3;
    const float dp0 = Pp[0] - Cc[0];
    const float dp1 = Pp[1] - Cc[1];
    const float dp2 = Pp[2] - Cc[2];
    __syncthreads();

    float* ht = S.buf;

    // ---- h1 k-major ----
    {
        const float4* F1p = (const float4*)&g_F1[((size_t)b * NPTS + jl) * HID];
#pragma unroll
        for (int q = 0; q < 16; q++) {
            float4 f = __ldg(F1p + q);
#pragma unroll
            for (int e = 0; e < 4; e++) {
                int k = 4*q + e;
                float4 w = S.wb1[k];
                float fe = (e == 0) ? f.x : (e == 1) ? f.y : (e == 2) ? f.z : f.w;
                float v  = fe + dp0*w.x + dp1*w.y + dp2*w.z + w.w;
                ht[k*HT_STRIDE + n] = fmaxf(v, 0.0f);
            }
        }
    }
    __syncthreads();

    const int rg = tid >> 3, cg = tid & 7;
    const int r0 = rg * 8, cbase = cg * 8;
    const int rsw = rg & 7;

    // ---- h2: 128x64x64, 8x8 tiles, FFMA2 ----
    ull acc[8][4];
    {
        ull binit[4];
#pragma unroll
        for (int p = 0; p < 4; p++) binit[p] = *(const ull*)&S.b2[cbase + 2*p];
#pragma unroll
        for (int r = 0; r < 8; r++)
#pragma unroll
            for (int p = 0; p < 4; p++) acc[r][p] = binit[p];
    }
#pragma unroll 4
    for (int k = 0; k < 64; k++) {
        float4 a0 = *(const float4*)(ht + k*HT_STRIDE + r0);
        float4 a1 = *(const float4*)(ht + k*HT_STRIDE + r0 + 4);
        ull aa[8];
        aa[0]=pk2(a0.x,a0.x); aa[1]=pk2(a0.y,a0.y); aa[2]=pk2(a0.z,a0.z); aa[3]=pk2(a0.w,a0.w);
        aa[4]=pk2(a1.x,a1.x); aa[5]=pk2(a1.y,a1.y); aa[6]=pk2(a1.z,a1.z); aa[7]=pk2(a1.w,a1.w);
        const ulonglong2* wr = (const ulonglong2*)(W2 + (size_t)k * 64 + cbase);
        ulonglong2 wv = __ldg(wr);
        ull wp[4]; wp[0] = wv.x; wp[1] = wv.y;
        ulonglong2 wv2 = __ldg(wr + 1);
        wp[2] = wv2.x; wp[3] = wv2.y;
#pragma unroll
        for (int r = 0; r < 8; r++)
#pragma unroll
            for (int p = 0; p < 4; p++) fma2(acc[r][p], aa[r], wp[p]);
    }
    __syncthreads();

    // ---- relu + swizzled row-major writeback ----
    float* h2r = S.buf;
#pragma unroll
    for (int r = 0; r < 8; r++) {
        float* rowp = h2r + (r0 + r) * H2_STRIDE;
#pragma unroll
        for (int p = 0; p < 4; p++) {
            float2 v = upk2(acc[r][p]);
            float2 rv = make_float2(fmaxf(v.x, 0.0f), fmaxf(v.y, 0.0f));
            int c4   = (cbase >> 2) + (p >> 1);
            int slot = c4 ^ rsw;
            *(float2*)(rowp + (slot << 2) + ((2*p) & 3)) = rv;
        }
    }
    __syncthreads();

    // ---- h3: 128x128x64 in two halves ----
    const int cn = S.cnt[rg >> 3];
#pragma unroll
    for (int half = 0; half < 2; half++) {
        ull acc3[8][4];
        {
            ull binit[4];
#pragma unroll
            for (int p = 0; p < 4; p++)
                binit[p] = *(const ull*)&S.b3[half*64 + cbase + 2*p];
#pragma unroll
            for (int r = 0; r < 8; r++)
#pragma unroll
                for (int p = 0; p < 4; p++) acc3[r][p] = binit[p];
        }
#pragma unroll 2
        for (int kc = 0; kc < 16; kc++) {
            float ar[8][4];
#pragma unroll
            for (int r = 0; r < 8; r++) {
                int slot = kc ^ rsw;
                *(float4*)ar[r] = *(const float4*)(h2r + (r0 + r)*H2_STRIDE + (slot << 2));
            }
#pragma unroll
            for (int e = 0; e < 4; e++) {
                int k = kc*4 + e;
                ull aa[8];
#pragma unroll
                for (int r = 0; r < 8; r++) aa[r] = pk2(ar[r][e], ar[r][e]);
                const ulonglong2* wr = (const ulonglong2*)(W3 + (size_t)k * OUTC + half*64 + cbase);
                ulonglong2 wv = __ldg(wr);
                ull wp[4]; wp[0] = wv.x; wp[1] = wv.y;
                ulonglong2 wv2 = __ldg(wr + 1);
                wp[2] = wv2.x; wp[3] = wv2.y;
#pragma unroll
                for (int r = 0; r < 8; r++)
#pragma unroll
                    for (int p = 0; p < 4; p++) fma2(acc3[r][p], aa[r], wp[p]);
            }
        }
        float cm[8];
#pragma unroll
        for (int c = 0; c < 8; c++) cm[c] = -CUDART_INF_F;
#pragma unroll
        for (int r = 0; r < 8; r++) {
            if (((r0 + r) & 63) < cn) {
#pragma unroll
                for (int p = 0; p < 4; p++) {
                    float2 v = upk2(acc3[r][p]);
                    cm[2*p]     = fmaxf(cm[2*p],     fmaxf(v.x, 0.0f));
                    cm[2*p + 1] = fmaxf(cm[2*p + 1], fmaxf(v.y, 0.0f));
                }
            }
        }
#pragma unroll
        for (int c = 0; c < 8; c++) S.cmax[rg][half*64 + cbase + c] = cm[c];
    }
    __syncthreads();

    float v0 = -CUDART_INF_F, v1 = -CUDART_INF_F;
#pragma unroll
    for (int g = 0; g < 8; g++) {
        v0 = fmaxf(v0, S.cmax[g][tid]);
        v1 = fmaxf(v1, S.cmax[8 + g][tid]);
    }
    out[(size_t)c0 * OUTC + tid]       = v0;
    out[(size_t)(c0 + 1) * OUTC + tid] = v1;
}

// =====================================================================
extern "C" void kernel_launch(void* const* d_in, const int* in_sizes, int n_in,
                              void* d_out, int out_size)
{
    const float *xyz = nullptr, *point = nullptr;
    const float *W1 = nullptr, *b1 = nullptr, *W2 = nullptr, *b2 = nullptr;
    const float *W3 = nullptr, *b3 = nullptr;
    for (int i = 0; i < n_in; i++) {
        switch (in_sizes[i]) {
            case 4194304: xyz   = (const float*)d_in[i]; break;
            case 196608:  point = (const float*)d_in[i]; break;
            case 4288:    W1    = (const float*)d_in[i]; break;
            case 4096:    W2    = (const float*)d_in[i]; break;
            case 8192:    W3    = (const float*)d_in[i]; break;
            case 128:     b3    = (const float*)d_in[i]; break;
            case 64:      if (!b1) b1 = (const float*)d_in[i];
                          else     b2 = (const float*)d_in[i];   break;
            default: break;
        }
    }

    float* out      = (float*)d_out;
    float* cenout   = out + (size_t)NCTR * OUTC;
    float* batchout = cenout + (size_t)NCTR * 3;

    fps_kernel<<<BCL, 256>>>(point, cenout, batchout);
    f1_kernel<<<(BCL * NPTS) / 64, 64>>>(xyz, W1);
    select_kernel<<<NCTR, 128>>>(point, cenout);
    mlp2_kernel<<<NCTR / 2, 128>>>(point, cenout, W1, b1, W2, b2, W3, b3, out);
}

// round 16
// speedup vs baseline: 1.7535x; 1.7535x over previous
#include <cuda_runtime.h>
#include <math_constants.h>
#include <cstdint>

#define BCL   16
#define NPTS  4096
#define MCTR  1024
#define CIN   64
#define HID   64
#define OUTC  128
#define KNBR  64
#define NCTR  (BCL*MCTR)

typedef unsigned long long ull;

// ---------------- device scratch (no allocs allowed) ----------------
__device__ float g_F1[(size_t)BCL*NPTS*HID];   // 16 MB: feat @ W1[0:64]
__device__ int   g_nbr[(size_t)NCTR*KNBR];
__device__ int   g_cnt[NCTR];

// d2 with NO fma contraction, left-assoc — must match XLA's sum((a-b)**2, -1)
__device__ __forceinline__ float d2_nofma(float dx, float dy, float dz) {
    return __fadd_rn(__fadd_rn(__fmul_rn(dx, dx), __fmul_rn(dy, dy)), __fmul_rn(dz, dz));
}

// ---------------- packed f32x2 helpers (sm_103a) ----------------
__device__ __forceinline__ ull pk2(float lo, float hi) {
    ull r;
    asm("mov.b64 %0, {%1, %2};" : "=l"(r)
        : "r"(__float_as_uint(lo)), "r"(__float_as_uint(hi)));
    return r;
}
__device__ __forceinline__ float2 upk2(ull v) {
    unsigned lo, hi;
    asm("mov.b64 {%0, %1}, %2;" : "=r"(lo), "=r"(hi) : "l"(v));
    return make_float2(__uint_as_float(lo), __uint_as_float(hi));
}
__device__ __forceinline__ ull mul2(ull a, ull b) {
    ull r; asm("mul.rn.f32x2 %0, %1, %2;" : "=l"(r) : "l"(a), "l"(b)); return r;
}
__device__ __forceinline__ ull add2(ull a, ull b) {
    ull r; asm("add.rn.f32x2 %0, %1, %2;" : "=l"(r) : "l"(a), "l"(b)); return r;
}
__device__ __forceinline__ void fma2(ull& d, ull a, ull b) {
    asm("fma.rn.f32x2 %0, %1, %2, %0;" : "+l"(d) : "l"(a), "l"(b));
}
__device__ __forceinline__ unsigned redux_max_u32(unsigned v) {
    unsigned r; asm("redux.sync.max.u32 %0, %1, 0xffffffff;" : "=r"(r) : "r"(v)); return r;
}
__device__ __forceinline__ unsigned redux_min_u32(unsigned v) {
    unsigned r; asm("redux.sync.min.u32 %0, %1, 0xffffffff;" : "=r"(r) : "r"(v)); return r;
}

// =====================================================================
// Kernel 1: FPS. 1 block/cloud, 256 threads x 16 pts in registers.
// Warp argmax via 2x redux.sync (max d2 bits, then min idx among maxers)
// — semantics identical to the u64-key shuffle chain, ~100 cyc shorter.
// =====================================================================
__global__ __launch_bounds__(256) void fps_kernel(
    const float* __restrict__ pos,
    float* __restrict__ out_centers, float* __restrict__ out_batch)
{
    const int b   = blockIdx.x;
    const int tid = threadIdx.x;
    const float* P = pos + (size_t)b * NPTS * 3;

    ull pxp[8], pyp[8], pzp[8];
    float dd[16];
#pragma unroll
    for (int q = 0; q < 8; q++) {
        int jA = tid + (q << 9);
        int jB = jA + 256;
        pxp[q] = pk2(P[3*jA],   P[3*jB]);
        pyp[q] = pk2(P[3*jA+1], P[3*jB+1]);
        pzp[q] = pk2(P[3*jA+2], P[3*jB+2]);
    }
#pragma unroll
    for (int i = 0; i < 16; i++) dd[i] = CUDART_INF_F;

    __shared__ ull s_wk[2][8];
    const int lane = tid & 31, wid = tid >> 5;

    int jwin = 0;
    for (int m = 0; m < MCTR; m++) {
        float cx = P[3*jwin], cy = P[3*jwin+1], cz = P[3*jwin+2];
        if (tid == 0) {
            size_t o = (size_t)b * MCTR + m;
            out_centers[o*3+0] = cx;
            out_centers[o*3+1] = cy;
            out_centers[o*3+2] = cz;
            out_batch[o] = (float)b;
        }
        if (m == MCTR - 1) break;

        const ull ncx = pk2(-cx, -cx), ncy = pk2(-cy, -cy), ncz = pk2(-cz, -cz);
        float bd = -1.0f; int bj = 0;
#pragma unroll
        for (int q = 0; q < 8; q++) {
            ull dx = add2(pxp[q], ncx);            // == px - cx (exact)
            ull dy = add2(pyp[q], ncy);
            ull dz = add2(pzp[q], ncz);
            ull d2p = add2(add2(mul2(dx, dx), mul2(dy, dy)), mul2(dz, dz));
            float2 d = upk2(d2p);
            float nA = fminf(dd[2*q],   d.x);
            float nB = fminf(dd[2*q+1], d.y);
            dd[2*q] = nA; dd[2*q+1] = nB;
            // per-thread j ascending, strict > keeps lowest index on ties
            if (nA > bd) { bd = nA; bj = tid + (q << 9); }
            if (nB > bd) { bd = nB; bj = tid + (q << 9) + 256; }
        }
        // warp argmax: bd >= 0 always after q=0, so float bits are monotone
        unsigned db = __float_as_uint(bd);
        unsigned wm = redux_max_u32(db);
        unsigned cand = (db == wm) ? (unsigned)bj : 0xFFFFFFFFu;
        unsigned wj = redux_min_u32(cand);
        if (lane == 0)
            s_wk[m & 1][wid] = ((ull)wm << 32) | (ull)(0xFFFFFFFFu - wj);
        __syncthreads();
        ull k0 = s_wk[m & 1][0];
#pragma unroll
        for (int w = 1; w < 8; w++) {
            ull kw = s_wk[m & 1][w];
            if (kw > k0) k0 = kw;
        }
        jwin = (int)(0xFFFFFFFFu - (unsigned)(k0 & 0xFFFFFFFFu));
    }
}

// =====================================================================
// Kernel 2: F1 = feat @ W1[0:64]  (unchanged)
// =====================================================================
__global__ __launch_bounds__(64) void f1_kernel(
    const float* __restrict__ feat, const float* __restrict__ W1)
{
    __shared__ float sf[64][65];
    __shared__ float sw[64][64];
    const int p0  = blockIdx.x * 64;
    const int tid = threadIdx.x;

    for (int i = tid; i < 4096; i += 64) sw[i >> 6][i & 63] = W1[i];
    for (int i = tid; i < 4096; i += 64) {
        int p = i >> 6, c = i & 63;
        sf[p][c] = feat[(size_t)(p0 + p) * CIN + c];
    }
    __syncthreads();

    const int c = tid;
    for (int p = 0; p < 64; p += 4) {
        float a0 = 0.f, a1 = 0.f, a2 = 0.f, a3 = 0.f;
#pragma unroll
        for (int k = 0; k < 64; k++) {
            float w = sw[k][c];
            a0 += sf[p+0][k] * w;
            a1 += sf[p+1][k] * w;
            a2 += sf[p+2][k] * w;
            a3 += sf[p+3][k] * w;
        }
        g_F1[(size_t)(p0+p+0)*HID + c] = a0;
        g_F1[(size_t)(p0+p+1)*HID + c] = a1;
        g_F1[(size_t)(p0+p+2)*HID + c] = a2;
        g_F1[(size_t)(p0+p+3)*HID + c] = a3;
    }
}

// =====================================================================
// Kernel 3: exact K-nearest-in-ball selection — COMPACT-FIRST.
// =====================================================================
__global__ __launch_bounds__(128) void select_kernel(
    const float* __restrict__ pos, const float* __restrict__ centers)
{
    const int cid = blockIdx.x;
    const int b   = cid >> 10;
    const int tid = threadIdx.x;
    const int lane = tid & 31, wid = tid >> 5;
    const float* P = pos + (size_t)b * NPTS * 3;

    __shared__ unsigned        cb[NPTS];     // compact d2 bits (worst case 4096)
    __shared__ unsigned short  ci[NPTS];     // compact original index
    __shared__ int hist[256];
    __shared__ int s_wsum[4];
    __shared__ int s_cnt, s_pos, s_bin, s_klt, s_eqn;
    __shared__ int s_eq[64];

    const float cx = centers[(size_t)cid*3+0];
    const float cy = centers[(size_t)cid*3+1];
    const float cz = centers[(size_t)cid*3+2];
    const float R2 = (float)(0.2 * 0.2);

    if (tid == 0) { s_cnt = 0; s_pos = 0; s_eqn = 0; }
    __syncthreads();

    // ---- phase 1: distances + compaction of valid entries ----
    for (int j = tid; j < NPTS; j += 128) {
        float dx = cx - P[3*j], dy = cy - P[3*j+1], dz = cz - P[3*j+2];
        float d2 = d2_nofma(dx, dy, dz);
        if (d2 < R2) {
            int p = atomicAdd(&s_cnt, 1);
            cb[p] = __float_as_uint(d2);
            ci[p] = (unsigned short)j;
        }
    }
    __syncthreads();
    const int cnt = s_cnt;

    if (cnt <= KNBR) {                        // take every valid neighbor
        for (int p = tid; p < KNBR; p += 128)
            g_nbr[(size_t)cid*KNBR + p] = (p < cnt) ? (int)ci[p] : 0;
        if (tid == 0) g_cnt[cid] = cnt;
        return;
    }

    // ---- radix select over the COMPACT list: 64th smallest ----
    unsigned pref = 0; int k = KNBR;
    for (int sh = 24; sh >= 0; sh -= 8) {
        for (int i = tid; i < 256; i += 128) hist[i] = 0;
        __syncthreads();
        unsigned hm = (sh == 24) ? 0u : (0xFFFFFFFFu << (sh + 8));
        for (int p = tid; p < cnt; p += 128) {
            unsigned v = cb[p];
            if ((v & hm) == pref)
                atomicAdd(&hist[(v >> sh) & 255], 1);
        }
        __syncthreads();
        {
            int h0 = hist[2*tid], h1 = hist[2*tid+1];
            int loc = h0 + h1;
            int inc = loc;
#pragma unroll
            for (int off = 1; off < 32; off <<= 1) {
                int t = __shfl_up_sync(0xFFFFFFFFu, inc, off);
                if (lane >= off) inc += t;
            }
            if (lane == 31) s_wsum[wid] = inc;
            __syncthreads();
            int woff = 0;
#pragma unroll
            for (int w = 0; w < 4; w++) if (w < wid) woff += s_wsum[w];
            int cumIncl   = inc + woff;
            int cumBefore = cumIncl - loc;
            if (cumBefore < k && k <= cumBefore + h0) {
                s_bin = 2*tid;     s_klt = k - cumBefore;
            } else if (cumBefore + h0 < k && k <= cumIncl) {
                s_bin = 2*tid + 1; s_klt = k - cumBefore - h0;
            }
        }
        __syncthreads();
        pref |= ((unsigned)s_bin) << sh;
        k = s_klt;
        __syncthreads();
    }
    const unsigned T = pref;   // exact 64th smallest; k = rank within equals

    // ---- emission from the compact list ----
    for (int p = tid; p < cnt; p += 128) {
        unsigned v = cb[p];
        if (v < T) {
            int q = atomicAdd(&s_pos, 1);
            g_nbr[(size_t)cid*KNBR + q] = (int)ci[p];
        } else if (v == T) {
            int e = atomicAdd(&s_eqn, 1);
            if (e < 64) s_eq[e] = (int)ci[p];
        }
    }
    __syncthreads();
    if (tid == 0) {
        int base = s_pos;                 // = 64 - k
        int ne = s_eqn < 64 ? s_eqn : 64;
        for (int a = 1; a < ne; a++) {    // ascending index (stable-top_k ties)
            int key = s_eq[a], t2 = a - 1;
            while (t2 >= 0 && s_eq[t2] > key) { s_eq[t2+1] = s_eq[t2]; t2--; }
            s_eq[t2+1] = key;
        }
        for (int a = 0; a < k; a++) g_nbr[(size_t)cid*KNBR + base + a] = s_eq[a];
        g_cnt[cid] = KNBR;
    }
}

// =====================================================================
// Kernel 4: fused MLP + masked max (R11 version, measured best 610us).
// =====================================================================
#define HT_STRIDE 136     // ht[64][136]  (k-major view)
#define H2_STRIDE 68      // h2row[128][68] (row-major swizzled view)

struct __align__(16) Mlp2Smem {
    float  buf[64 * HT_STRIDE];
    float  cmax[16][132];
    float4 wb1[64];
    float  b2[64];
    float  b3[128];
    int    cnt[2];
};

__global__ __launch_bounds__(128, 4) void mlp2_kernel(
    const float* __restrict__ pos, const float* __restrict__ centers,
    const float* __restrict__ W1, const float* __restrict__ b1,
    const float* __restrict__ W2, const float* __restrict__ b2,
    const float* __restrict__ W3, const float* __restrict__ b3,
    float* __restrict__ out)
{
    __shared__ Mlp2Smem S;

    const int c0  = blockIdx.x * 2;
    const int b   = c0 >> 10;
    const int tid = threadIdx.x;

    if (tid < 64) {
        S.wb1[tid] = make_float4(W1[4096 + tid], W1[4160 + tid], W1[4224 + tid], b1[tid]);
        S.b2[tid]  = b2[tid];
    }
    S.b3[tid] = b3[tid];
    if (tid < 2) S.cnt[tid] = g_cnt[c0 + tid];

    const int n      = tid;
    const int center = n >> 6;
    const int jl     = g_nbr[(size_t)c0 * KNBR + n];
    const float* Pp  = pos + ((size_t)b * NPTS + jl) * 3;
    const float* Cc  = centers + (size_t)(c0 + center) * 3;
    const float dp0 = Pp[0] - Cc[0];
    const float dp1 = Pp[1] - Cc[1];
    const float dp2 = Pp[2] - Cc[2];
    __syncthreads();

    float* ht = S.buf;

    // ---- h1 k-major ----
    {
        const float4* F1p = (const float4*)&g_F1[((size_t)b * NPTS + jl) * HID];
#pragma unroll
        for (int q = 0; q < 16; q++) {
            float4 f = __ldg(F1p + q);
#pragma unroll
            for (int e = 0; e < 4; e++) {
                int k = 4*q + e;
                float4 w = S.wb1[k];
                float fe = (e == 0) ? f.x : (e == 1) ? f.y : (e == 2) ? f.z : f.w;
                float v  = fe + dp0*w.x + dp1*w.y + dp2*w.z + w.w;
                ht[k*HT_STRIDE + n] = fmaxf(v, 0.0f);
            }
        }
    }
    __syncthreads();

    const int rg = tid >> 3, cg = tid & 7;
    const int r0 = rg * 8, cbase = cg * 8;
    const int rsw = rg & 7;

    // ---- h2: 128x64x64, 8x8 tiles, FFMA2 ----
    ull acc[8][4];
    {
        ull binit[4];
#pragma unroll
        for (int p = 0; p < 4; p++) binit[p] = *(const ull*)&S.b2[cbase + 2*p];
#pragma unroll
        for (int r = 0; r < 8; r++)
#pragma unroll
            for (int p = 0; p < 4; p++) acc[r][p] = binit[p];
    }
#pragma unroll 4
    for (int k = 0; k < 64; k++) {
        float4 a0 = *(const float4*)(ht + k*HT_STRIDE + r0);
        float4 a1 = *(const float4*)(ht + k*HT_STRIDE + r0 + 4);
        ull aa[8];
        aa[0]=pk2(a0.x,a0.x); aa[1]=pk2(a0.y,a0.y); aa[2]=pk2(a0.z,a0.z); aa[3]=pk2(a0.w,a0.w);
        aa[4]=pk2(a1.x,a1.x); aa[5]=pk2(a1.y,a1.y); aa[6]=pk2(a1.z,a1.z); aa[7]=pk2(a1.w,a1.w);
        const ulonglong2* wr = (const ulonglong2*)(W2 + (size_t)k * 64 + cbase);
        ulonglong2 wv = __ldg(wr);
        ull wp[4]; wp[0] = wv.x; wp[1] = wv.y;
        ulonglong2 wv2 = __ldg(wr + 1);
        wp[2] = wv2.x; wp[3] = wv2.y;
#pragma unroll
        for (int r = 0; r < 8; r++)
#pragma unroll
            for (int p = 0; p < 4; p++) fma2(acc[r][p], aa[r], wp[p]);
    }
    __syncthreads();

    // ---- relu + swizzled row-major writeback ----
    float* h2r = S.buf;
#pragma unroll
    for (int r = 0; r < 8; r++) {
        float* rowp = h2r + (r0 + r) * H2_STRIDE;
#pragma unroll
        for (int p = 0; p < 4; p++) {
            float2 v = upk2(acc[r][p]);
            float2 rv = make_float2(fmaxf(v.x, 0.0f), fmaxf(v.y, 0.0f));
            int c4   = (cbase >> 2) + (p >> 1);
            int slot = c4 ^ rsw;
            *(float2*)(rowp + (slot << 2) + ((2*p) & 3)) = rv;
        }
    }
    __syncthreads();

    // ---- h3: 128x128x64 in two halves ----
    const int cn = S.cnt[rg >> 3];
#pragma unroll
    for (int half = 0; half < 2; half++) {
        ull acc3[8][4];
        {
            ull binit[4];
#pragma unroll
            for (int p = 0; p < 4; p++)
                binit[p] = *(const ull*)&S.b3[half*64 + cbase + 2*p];
#pragma unroll
            for (int r = 0; r < 8; r++)
#pragma unroll
                for (int p = 0; p < 4; p++) acc3[r][p] = binit[p];
        }
#pragma unroll 2
        for (int kc = 0; kc < 16; kc++) {
            float ar[8][4];
#pragma unroll
            for (int r = 0; r < 8; r++) {
                int slot = kc ^ rsw;
                *(float4*)ar[r] = *(const float4*)(h2r + (r0 + r)*H2_STRIDE + (slot << 2));
            }
#pragma unroll
            for (int e = 0; e < 4; e++) {
                int k = kc*4 + e;
                ull aa[8];
#pragma unroll
                for (int r = 0; r < 8; r++) aa[r] = pk2(ar[r][e], ar[r][e]);
                const ulonglong2* wr = (const ulonglong2*)(W3 + (size_t)k * OUTC + half*64 + cbase);
                ulonglong2 wv = __ldg(wr);
                ull wp[4]; wp[0] = wv.x; wp[1] = wv.y;
                ulonglong2 wv2 = __ldg(wr + 1);
                wp[2] = wv2.x; wp[3] = wv2.y;
#pragma unroll
                for (int r = 0; r < 8; r++)
#pragma unroll
                    for (int p = 0; p < 4; p++) fma2(acc3[r][p], aa[r], wp[p]);
            }
        }
        float cm[8];
#pragma unroll
        for (int c = 0; c < 8; c++) cm[c] = -CUDART_INF_F;
#pragma unroll
        for (int r = 0; r < 8; r++) {
            if (((r0 + r) & 63) < cn) {
#pragma unroll
                for (int p = 0; p < 4; p++) {
                    float2 v = upk2(acc3[r][p]);
                    cm[2*p]     = fmaxf(cm[2*p],     fmaxf(v.x, 0.0f));
                    cm[2*p + 1] = fmaxf(cm[2*p + 1], fmaxf(v.y, 0.0f));
                }
            }
        }
#pragma unroll
        for (int c = 0; c < 8; c++) S.cmax[rg][half*64 + cbase + c] = cm[c];
    }
    __syncthreads();

    float v0 = -CUDART_INF_F, v1 = -CUDART_INF_F;
#pragma unroll
    for (int g = 0; g < 8; g++) {
        v0 = fmaxf(v0, S.cmax[g][tid]);
        v1 = fmaxf(v1, S.cmax[8 + g][tid]);
    }
    out[(size_t)c0 * OUTC + tid]       = v0;
    out[(size_t)(c0 + 1) * OUTC + tid] = v1;
}

// =====================================================================
extern "C" void kernel_launch(void* const* d_in, const int* in_sizes, int n_in,
                              void* d_out, int out_size)
{
    const float *xyz = nullptr, *point = nullptr;
    const float *W1 = nullptr, *b1 = nullptr, *W2 = nullptr, *b2 = nullptr;
    const float *W3 = nullptr, *b3 = nullptr;
    for (int i = 0; i < n_in; i++) {
        switch (in_sizes[i]) {
            case 4194304: xyz   = (const float*)d_in[i]; break;
            case 196608:  point = (const float*)d_in[i]; break;
            case 4288:    W1    = (const float*)d_in[i]; break;
            case 4096:    W2    = (const float*)d_in[i]; break;
            case 8192:    W3    = (const float*)d_in[i]; break;
            case 128:     b3    = (const float*)d_in[i]; break;
            case 64:      if (!b1) b1 = (const float*)d_in[i];
                          else     b2 = (const float*)d_in[i];   break;
            default: break;
        }
    }

    float* out      = (float*)d_out;
    float* cenout   = out + (size_t)NCTR * OUTC;
    float* batchout = cenout + (size_t)NCTR * 3;

    fps_kernel<<<BCL, 256>>>(point, cenout, batchout);
    f1_kernel<<<(BCL * NPTS) / 64, 64>>>(xyz, W1);
    select_kernel<<<NCTR, 128>>>(point, cenout);
    mlp2_kernel<<<NCTR / 2, 128>>>(point, cenout, W1, b1, W2, b2, W3, b3, out);
}